// round 1
// baseline (speedup 1.0000x reference)
#include <cuda_runtime.h>

#define TT 33
#define CC 512
#define DK 64
#define NJ 192          // 3*DK (q,k,v concatenated)
#define CTILE 64        // contraction tile
#define NTHREADS 256

// t padded to 40 so the 5x8 t-tiling (t = tt + 8*i, i<5 -> t<=39) never reads OOB.
struct Smem {
    float xs[CC][40];        // x^T: [c][t], t>=33 zero-filled
    float ws[CTILE][200];    // W tile: [c][j]
    float qkv[TT][196];      // [t][j]; q = [0,64), k = [64,128), v = [128,192)
    float sc[TT][TT];        // scores -> softmax weights
};

__global__ __launch_bounds__(NTHREADS, 1)
void head_kernel(const float* __restrict__ x,
                 const float* __restrict__ Wq,
                 const float* __restrict__ Wk,
                 const float* __restrict__ Wv,
                 float* __restrict__ out) {
    extern __shared__ char smem_raw[];
    Smem& s = *reinterpret_cast<Smem*>(smem_raw);

    const int b = blockIdx.x;
    const int tid = threadIdx.x;
    const float* xb = x + (size_t)b * TT * CC;

    // ---- Stage x transposed into SMEM. t-fast mapping: consecutive lanes hit
    // consecutive t -> consecutive banks on the strided stores (conflict-free).
    for (int idx = tid; idx < TT * (CC / 4); idx += NTHREADS) {
        int t  = idx % TT;
        int c4 = idx / TT;                 // 0..127
        float4 v = *(const float4*)(xb + t * CC + c4 * 4);
        s.xs[c4 * 4 + 0][t] = v.x;
        s.xs[c4 * 4 + 1][t] = v.y;
        s.xs[c4 * 4 + 2][t] = v.z;
        s.xs[c4 * 4 + 3][t] = v.w;
    }
    // Zero-fill padded t columns so inactive accumulators stay finite.
    for (int c = tid; c < CC; c += NTHREADS) {
        #pragma unroll
        for (int tp = TT; tp < 40; ++tp) s.xs[c][tp] = 0.f;
    }

    // ---- QKV projection: out[t][j] = sum_c x[t][c] * W[j][c]
    // Thread tile: 5 t-values x 6 j-values per thread.
    const int tj = tid >> 3;   // 0..31  (j = tj + 32*jj)
    const int tt = tid & 7;    // 0..7   (t = tt + 8*i)

    float acc[5][6];
    #pragma unroll
    for (int i = 0; i < 5; ++i)
        #pragma unroll
        for (int j = 0; j < 6; ++j) acc[i][j] = 0.f;

    for (int c0 = 0; c0 < CC; c0 += CTILE) {
        __syncthreads();   // xs staged (iter 0) / previous tile consumed (iter >0)
        // Stage W tile as [c][j]
        for (int idx = tid; idx < NJ * (CTILE / 4); idx += NTHREADS) {  // 3072
            int j  = idx >> 4;
            int cq = (idx & 15) << 2;
            const float* src = (j < DK)     ? (Wq + j * CC)
                             : (j < 2 * DK) ? (Wk + (j - DK) * CC)
                                            : (Wv + (j - 2 * DK) * CC);
            float4 w = *(const float4*)(src + c0 + cq);
            s.ws[cq + 0][j] = w.x;
            s.ws[cq + 1][j] = w.y;
            s.ws[cq + 2][j] = w.z;
            s.ws[cq + 3][j] = w.w;
        }
        __syncthreads();

        #pragma unroll 2
        for (int c = 0; c < CTILE; ++c) {
            float xv[5], wv[6];
            #pragma unroll
            for (int i = 0; i < 5; ++i) xv[i] = s.xs[c0 + c][tt + 8 * i];
            #pragma unroll
            for (int j = 0; j < 6; ++j) wv[j] = s.ws[c][tj + 32 * j];
            #pragma unroll
            for (int i = 0; i < 5; ++i)
                #pragma unroll
                for (int j = 0; j < 6; ++j)
                    acc[i][j] = fmaf(xv[i], wv[j], acc[i][j]);
        }
    }
    __syncthreads();

    // ---- Write qkv tiles to SMEM
    #pragma unroll
    for (int i = 0; i < 5; ++i) {
        int t = tt + 8 * i;
        if (t < TT) {
            #pragma unroll
            for (int j = 0; j < 6; ++j)
                s.qkv[t][tj + 32 * j] = acc[i][j];
        }
    }
    __syncthreads();

    // ---- Scores: sc[t][ss] = (q[t] . k[ss]) * C^-0.5, causal (ss <= t)
    const float scale = 0.044194173824159216f;  // 512^-0.5
    for (int idx = tid; idx < TT * TT; idx += NTHREADS) {
        int t  = idx / TT;
        int ss = idx % TT;
        if (ss <= t) {
            const float4* qp = (const float4*)&s.qkv[t][0];
            const float4* kp = (const float4*)&s.qkv[ss][DK];
            float a = 0.f;
            #pragma unroll
            for (int dq = 0; dq < DK / 4; ++dq) {
                float4 qv = qp[dq];
                float4 kv = kp[dq];
                a += qv.x * kv.x + qv.y * kv.y + qv.z * kv.z + qv.w * kv.w;
            }
            s.sc[t][ss] = a * scale;
        }
    }
    __syncthreads();

    // ---- Causal softmax, one thread per row
    if (tid < TT) {
        int t = tid;
        float m = s.sc[t][0];
        for (int ss = 1; ss <= t; ++ss) m = fmaxf(m, s.sc[t][ss]);
        float sum = 0.f;
        for (int ss = 0; ss <= t; ++ss) {
            float e = __expf(s.sc[t][ss] - m);
            s.sc[t][ss] = e;
            sum += e;
        }
        float inv = 1.f / sum;
        for (int ss = 0; ss <= t; ++ss) s.sc[t][ss] *= inv;
    }
    __syncthreads();

    // ---- out[t][d] = sum_{ss<=t} wei[t][ss] * v[ss][d]  (coalesced store)
    float* ob = out + (size_t)b * TT * DK;
    for (int idx = tid; idx < TT * DK; idx += NTHREADS) {
        int t = idx / DK;
        int d = idx % DK;
        float a = 0.f;
        for (int ss = 0; ss <= t; ++ss)
            a = fmaf(s.sc[t][ss], s.qkv[ss][2 * DK + d], a);
        ob[idx] = a;
    }
}

extern "C" void kernel_launch(void* const* d_in, const int* in_sizes, int n_in,
                              void* d_out, int out_size) {
    const float* x  = (const float*)d_in[0];
    const float* Wq = (const float*)d_in[1];
    const float* Wk = (const float*)d_in[2];
    const float* Wv = (const float*)d_in[3];
    float* out = (float*)d_out;

    int B = in_sizes[0] / (TT * CC);
    int smem = (int)sizeof(Smem);
    cudaFuncSetAttribute(head_kernel, cudaFuncAttributeMaxDynamicSharedMemorySize, smem);
    head_kernel<<<B, NTHREADS, smem>>>(x, Wq, Wk, Wv, out);
}

// round 3
// speedup vs baseline: 6.1282x; 6.1282x over previous
#include <cuda_runtime.h>
#include <cstdint>

#define BB 4096
#define TT 33
#define CC 512
#define DK 64
#define NJ 192           // 3*DK
#define MT 128           // CTA M tile
#define KC 32            // K chunk
#define PITCH 36         // smem row pitch in floats (bank-conflict-free fragments)
#define NT1 256

// Scratch (static __device__ arrays are the allowed scratch mechanism)
__device__ float g_wt[NJ * CC];                       // tf32-rounded W, [n][c]
__device__ float g_qkv[(size_t)BB * TT * NJ];         // qkv rows, [m][n]

__device__ __forceinline__ uint32_t f2tf32(float f) {
    uint32_t u;
    asm("cvt.rna.tf32.f32 %0, %1;" : "=r"(u) : "f"(f));
    return u;
}

__device__ __forceinline__ void mma_tf32(float* d, const uint32_t* a, const uint32_t* b) {
    asm volatile(
        "mma.sync.aligned.m16n8k8.row.col.f32.tf32.tf32.f32 "
        "{%0,%1,%2,%3}, {%4,%5,%6,%7}, {%8,%9}, {%0,%1,%2,%3};\n"
        : "+f"(d[0]), "+f"(d[1]), "+f"(d[2]), "+f"(d[3])
        : "r"(a[0]), "r"(a[1]), "r"(a[2]), "r"(a[3]), "r"(b[0]), "r"(b[1]));
}

__device__ __forceinline__ void cp_async16(void* smem_dst, const void* gsrc) {
    uint32_t s = (uint32_t)__cvta_generic_to_shared(smem_dst);
    asm volatile("cp.async.cg.shared.global [%0], [%1], 16;\n" :: "r"(s), "l"(gsrc));
}
#define CP_COMMIT() asm volatile("cp.async.commit_group;\n" ::: "memory")
#define CP_WAIT0()  asm volatile("cp.async.wait_group 0;\n" ::: "memory")

// ---------------- prep: W -> tf32-rounded, concatenated [192][512] ----------------
__global__ void prep_w(const float* __restrict__ Wq, const float* __restrict__ Wk,
                       const float* __restrict__ Wv) {
    int i = blockIdx.x * blockDim.x + threadIdx.x;
    if (i < NJ * CC) {
        int n = i / CC, c = i - n * CC;
        float v = (n < DK)     ? Wq[n * CC + c]
                : (n < 2 * DK) ? Wk[(n - DK) * CC + c]
                               : Wv[(n - 2 * DK) * CC + c];
        g_wt[i] = __uint_as_float(f2tf32(v));
    }
}

// ---------------- GEMM: g_qkv[m][n] = sum_c x[m][c] * W[n][c] (tf32 MMA) ----------
__global__ __launch_bounds__(NT1, 1)
void qkv_gemm(const float* __restrict__ x, size_t Mtot) {
    extern __shared__ float sm[];
    float* Asb[2] = { sm,                 sm + MT * PITCH };
    float* Bsb[2] = { sm + 2 * MT * PITCH, sm + 2 * MT * PITCH + NJ * PITCH };

    const int tid  = threadIdx.x;
    const int wid  = tid >> 5, lane = tid & 31;
    const int wm   = wid & 1;          // 0..1 -> m offset 64*wm
    const int wn   = wid >> 1;         // 0..3 -> n offset 48*wn
    const int g    = lane >> 2;        // 0..7
    const int tg   = lane & 3;         // 0..3
    const int r0   = tid >> 3;         // 0..31 (staging row)
    const int q    = tid & 7;          // 0..7  (staging float4 col)
    const size_t mbase = (size_t)blockIdx.x * MT;

    float acc[4][6][4];
    #pragma unroll
    for (int i = 0; i < 4; ++i)
        #pragma unroll
        for (int j = 0; j < 6; ++j)
            #pragma unroll
            for (int e = 0; e < 4; ++e) acc[i][j][e] = 0.f;

    float4 areg[4];

    // ---- prologue: chunk 0
    #pragma unroll
    for (int j = 0; j < 6; ++j) {        // B chunk 0 -> buf 0
        int n = r0 + 32 * j;
        cp_async16(&Bsb[0][n * PITCH + q * 4], g_wt + (size_t)n * CC + q * 4);
    }
    CP_COMMIT();
    #pragma unroll
    for (int i = 0; i < 4; ++i) {        // A chunk 0 -> regs
        size_t m = mbase + r0 + 32 * i;
        areg[i] = (m < Mtot) ? *(const float4*)(x + m * CC + q * 4)
                             : make_float4(0.f, 0.f, 0.f, 0.f);
    }

    for (int kt = 0; kt < CC / KC; ++kt) {
        const int buf = kt & 1;
        __syncthreads();                 // buffers free for reuse
        // STS A (tf32-rounded)
        #pragma unroll
        for (int i = 0; i < 4; ++i) {
            float4 v;
            v.x = __uint_as_float(f2tf32(areg[i].x));
            v.y = __uint_as_float(f2tf32(areg[i].y));
            v.z = __uint_as_float(f2tf32(areg[i].z));
            v.w = __uint_as_float(f2tf32(areg[i].w));
            *(float4*)&Asb[buf][(r0 + 32 * i) * PITCH + q * 4] = v;
        }
        CP_WAIT0();                      // B chunk kt arrived
        __syncthreads();                 // A STS + B async visible to all

        if (kt + 1 < CC / KC) {          // prefetch chunk kt+1
            const int nb = buf ^ 1;
            #pragma unroll
            for (int j = 0; j < 6; ++j) {
                int n = r0 + 32 * j;
                cp_async16(&Bsb[nb][n * PITCH + q * 4],
                           g_wt + (size_t)n * CC + (kt + 1) * KC + q * 4);
            }
            CP_COMMIT();
            #pragma unroll
            for (int i = 0; i < 4; ++i) {
                size_t m = mbase + r0 + 32 * i;
                areg[i] = (m < Mtot) ? *(const float4*)(x + m * CC + (kt + 1) * KC + q * 4)
                                     : make_float4(0.f, 0.f, 0.f, 0.f);
            }
        }

        // ---- compute chunk kt
        const uint32_t* Au = (const uint32_t*)Asb[buf];
        const uint32_t* Bu = (const uint32_t*)Bsb[buf];
        #pragma unroll
        for (int k8 = 0; k8 < KC / 8; ++k8) {
            const int kc0 = k8 * 8 + tg;
            uint32_t af[4][4];
            #pragma unroll
            for (int am = 0; am < 4; ++am) {
                int row = wm * 64 + am * 16 + g;
                af[am][0] = Au[row * PITCH + kc0];
                af[am][1] = Au[(row + 8) * PITCH + kc0];
                af[am][2] = Au[row * PITCH + kc0 + 4];
                af[am][3] = Au[(row + 8) * PITCH + kc0 + 4];
            }
            uint32_t bf[6][2];
            #pragma unroll
            for (int an = 0; an < 6; ++an) {
                int col = wn * 48 + an * 8 + g;
                bf[an][0] = Bu[col * PITCH + kc0];
                bf[an][1] = Bu[col * PITCH + kc0 + 4];
            }
            #pragma unroll
            for (int am = 0; am < 4; ++am)
                #pragma unroll
                for (int an = 0; an < 6; ++an)
                    mma_tf32(acc[am][an], af[am], bf[an]);
        }
    }

    // ---- epilogue: direct STG.64 of accumulators
    #pragma unroll
    for (int am = 0; am < 4; ++am) {
        size_t row = mbase + wm * 64 + am * 16 + g;
        #pragma unroll
        for (int an = 0; an < 6; ++an) {
            int col = wn * 48 + an * 8 + tg * 2;
            if (row < Mtot)
                *(float2*)&g_qkv[row * NJ + col] =
                    make_float2(acc[am][an][0], acc[am][an][1]);
            if (row + 8 < Mtot)
                *(float2*)&g_qkv[(row + 8) * NJ + col] =
                    make_float2(acc[am][an][2], acc[am][an][3]);
        }
    }
}

// ---------------- attention: per-batch causal softmax + PV ----------------
#define QP 196
#define SP 34
__global__ __launch_bounds__(128)
void attn(float* __restrict__ out) {
    __shared__ float qk[TT * QP];
    __shared__ float sc[TT * SP];
    const int b = blockIdx.x, tid = threadIdx.x;
    const float* src = g_qkv + (size_t)b * TT * NJ;

    for (int i4 = tid; i4 < TT * NJ / 4; i4 += 128) {
        int e = i4 * 4;
        int row = e / NJ, col = e - row * NJ;
        *(float4*)&qk[row * QP + col] = *(const float4*)(src + e);
    }
    __syncthreads();

    const float scale = 0.044194173824159216f;   // 512^-0.5
    for (int idx = tid; idx < TT * TT; idx += 128) {
        int t = idx / TT, ss = idx - t * TT;
        if (ss <= t) {
            const float4* qp = (const float4*)&qk[t * QP];
            const float4* kp = (const float4*)&qk[ss * QP + DK];
            float a = 0.f;
            #pragma unroll
            for (int dq = 0; dq < DK / 4; ++dq) {
                float4 qv = qp[dq], kv = kp[dq];
                a += qv.x * kv.x + qv.y * kv.y + qv.z * kv.z + qv.w * kv.w;
            }
            sc[t * SP + ss] = a * scale;
        }
    }
    __syncthreads();

    if (tid < TT) {
        int t = tid;
        float* row = sc + t * SP;
        float m = row[0];
        for (int ss = 1; ss <= t; ++ss) m = fmaxf(m, row[ss]);
        float sum = 0.f;
        for (int ss = 0; ss <= t; ++ss) {
            float e = __expf(row[ss] - m);
            row[ss] = e;
            sum += e;
        }
        float inv = 1.f / sum;
        for (int ss = 0; ss <= t; ++ss) row[ss] *= inv;
    }
    __syncthreads();

    float* ob = out + (size_t)b * TT * DK;
    for (int idx = tid; idx < TT * DK; idx += 128) {
        int t = idx / DK, d = idx - t * DK;
        float a = 0.f;
        for (int ss = 0; ss <= t; ++ss)
            a = fmaf(sc[t * SP + ss], qk[ss * QP + 2 * DK + d], a);
        ob[idx] = a;
    }
}

extern "C" void kernel_launch(void* const* d_in, const int* in_sizes, int n_in,
                              void* d_out, int out_size) {
    const float* x  = (const float*)d_in[0];
    const float* Wq = (const float*)d_in[1];
    const float* Wk = (const float*)d_in[2];
    const float* Wv = (const float*)d_in[3];
    float* out = (float*)d_out;

    int B = in_sizes[0] / (TT * CC);
    size_t Mtot = (size_t)B * TT;
    int gridG = (int)((Mtot + MT - 1) / MT);
    int smemG = (2 * MT * PITCH + 2 * NJ * PITCH) * 4;   // 92160 B

    prep_w<<<(NJ * CC + 255) / 256, 256>>>(Wq, Wk, Wv);
    cudaFuncSetAttribute(qkv_gemm, cudaFuncAttributeMaxDynamicSharedMemorySize, smemG);
    qkv_gemm<<<gridG, NT1, smemG>>>(x, Mtot);
    attn<<<B, 128>>>(out);
}